// round 1
// baseline (speedup 1.0000x reference)
#include <cuda_runtime.h>
#include <math.h>

// ---------------- problem constants ----------------
#define N_B   512
#define N_E   8
#define TOPK  2
#define CAPQ  160
#define N_C   10
#define T_C   256

// ---------------- device scratch (no allocations allowed) ----------------
__device__ float g_act0[512*32*32*32];   // layer0 out (relu), 32x32
__device__ float g_act1[512*64*16*16];   // layer1 out (relu+pool), 16x16
__device__ float g_act2[512*128*16*16];  // layer2 out (relu), 16x16
__device__ float g_feats[512*256];
__device__ float g_logits[512*8*10];
__device__ float g_conf[512*8];
__device__ int   g_D[512*8];
__device__ float g_scale[4*256];
__device__ float g_bias[4*256];

// ---------------- BN fold ----------------
__global__ void fold_kernel(const float* __restrict__ cb, const float* __restrict__ g,
                            const float* __restrict__ bt, const float* __restrict__ rm,
                            const float* __restrict__ rv, int nch, int layer)
{
    int c = threadIdx.x;
    if (c < nch) {
        float s = g[c] / sqrtf(rv[c] + 1e-5f);
        g_scale[layer*256 + c] = s;
        g_bias[layer*256 + c]  = cb[c]*s + bt[c] - rm[c]*s;
    }
}

// ---------------- direct conv3x3 + BN + ReLU (+pool, +mean) ----------------
// Block: 256 threads = 4 cout-groups(8 couts each) x 64 pos-threads(2x2 block).
// Grid: (COUT/32, (H/16)^2, B). Spatial tile 16x16, input smem tile 18x18 per cin.
template<int LAYER, int CIN, int CCH, int COUT, int H, bool POOL, bool MEAN>
__global__ __launch_bounds__(256, 2)
void conv_kernel(const float* __restrict__ x, const float* __restrict__ w)
{
    const float* in;
    if      (LAYER == 0) in = x;
    else if (LAYER == 1) in = g_act0;
    else if (LAYER == 2) in = g_act1;
    else                 in = g_act2;

    const int b   = blockIdx.z;
    const int ct  = blockIdx.x;
    const int ntx = H / 16;
    const int tyi = blockIdx.y / ntx, txi = blockIdx.y % ntx;
    const int ty0 = tyi * 16, tx0 = txi * 16;

    const int tid = threadIdx.x;
    const int cg  = tid >> 6;          // 0..3 -> 8 couts each
    const int p   = tid & 63;          // 0..63 -> 8x8 grid of 2x2 output blocks
    const int py  = p >> 3, px = p & 7;
    const int oy  = 2*py,  ox = 2*px;  // local output coords (top-left of 2x2)

    extern __shared__ float smem[];
    float* sIn = smem;                 // [CCH][18][18]
    float* sW  = smem + CCH*18*18;     // [CCH][32][9]

    float acc[4][8];
#pragma unroll
    for (int i = 0; i < 4; i++)
#pragma unroll
        for (int k = 0; k < 8; k++) acc[i][k] = 0.f;

    const int NCH = CIN / CCH;
    for (int ch = 0; ch < NCH; ch++) {
        if (ch) __syncthreads();
        const float* inb = in + ((long)b*CIN + (long)ch*CCH) * H * H;
        for (int i = tid; i < CCH*18*18; i += 256) {
            int c = i / 324; int r = i - c*324;
            int y = r / 18,  xx = r - y*18;
            int gy = ty0 + y - 1, gx = tx0 + xx - 1;
            float v = 0.f;
            if ((unsigned)gy < (unsigned)H && (unsigned)gx < (unsigned)H)
                v = inb[(long)c*H*H + gy*H + gx];
            sIn[i] = v;
        }
        for (int i = tid; i < CCH*32*9; i += 256) {
            int c = i / 288; int r = i - c*288;   // r = co_local*9 + tap
            int col = r / 9, t = r - col*9;
            sW[i] = w[(((long)(ct*32 + col))*CIN + ch*CCH + c)*9 + t];
        }
        __syncthreads();

        for (int c = 0; c < CCH; c++) {
            float iv[4][4];
            const float* sic = sIn + c*324 + oy*18 + ox;
#pragma unroll
            for (int dy = 0; dy < 4; dy++)
#pragma unroll
                for (int dx = 0; dx < 4; dx++)
                    iv[dy][dx] = sic[dy*18 + dx];
            const float* swc = sW + c*288 + cg*72;
#pragma unroll
            for (int k = 0; k < 8; k++) {
#pragma unroll
                for (int t = 0; t < 9; t++) {
                    const float wv = swc[k*9 + t];
                    const int dy = t / 3, dx = t % 3;
                    acc[0][k] = fmaf(iv[dy  ][dx  ], wv, acc[0][k]);
                    acc[1][k] = fmaf(iv[dy  ][dx+1], wv, acc[1][k]);
                    acc[2][k] = fmaf(iv[dy+1][dx  ], wv, acc[2][k]);
                    acc[3][k] = fmaf(iv[dy+1][dx+1], wv, acc[3][k]);
                }
            }
        }
    }

    // ---------- epilogue ----------
    float* outp;
    if      (LAYER == 0) outp = g_act0;
    else if (LAYER == 1) outp = g_act1;
    else if (LAYER == 2) outp = g_act2;
    else                 outp = g_feats;

    const int co0 = ct*32 + cg*8;
    if (!POOL) {
#pragma unroll
        for (int k = 0; k < 8; k++) {
            const float s  = g_scale[LAYER*256 + co0 + k];
            const float bi = g_bias [LAYER*256 + co0 + k];
#pragma unroll
            for (int r = 0; r < 2; r++)
#pragma unroll
                for (int s2 = 0; s2 < 2; s2++) {
                    float v = fmaxf(fmaf(acc[r*2+s2][k], s, bi), 0.f);
                    outp[(((long)b*COUT + co0 + k)*H + (ty0+oy+r))*H + (tx0+ox+s2)] = v;
                }
        }
    } else {
        float pooled[8];
#pragma unroll
        for (int k = 0; k < 8; k++) {
            const float s  = g_scale[LAYER*256 + co0 + k];
            const float bi = g_bias [LAYER*256 + co0 + k];
            float v0 = fmaf(acc[0][k], s, bi);
            float v1 = fmaf(acc[1][k], s, bi);
            float v2 = fmaf(acc[2][k], s, bi);
            float v3 = fmaf(acc[3][k], s, bi);
            pooled[k] = fmaxf(0.f, fmaxf(fmaxf(v0, v1), fmaxf(v2, v3)));
        }
        if (!MEAN) {
            const int Ho = H / 2;
            const int gy = ty0/2 + py, gx = tx0/2 + px;
#pragma unroll
            for (int k = 0; k < 8; k++)
                outp[(((long)b*COUT + co0 + k)*Ho + gy)*Ho + gx] = pooled[k];
        } else {
            // global mean over the 8x8 pooled map (block covers full plane)
            __syncthreads();
            float* sRed = smem;  // [64][33]
#pragma unroll
            for (int k = 0; k < 8; k++) sRed[p*33 + cg*8 + k] = pooled[k];
            __syncthreads();
            if (tid < 32) {
                float ssum = 0.f;
                for (int q = 0; q < 64; q++) ssum += sRed[q*33 + tid];
                outp[(long)b*256 + ct*32 + tid] = ssum * (1.0f/64.0f);
            }
        }
    }
}

// ---------------- classifier + log_softmax + conf ----------------
__global__ void classifier_kernel(const float* __restrict__ cls_w,
                                  const float* __restrict__ cls_b)
{
    const int b = blockIdx.x;
    const int tid = threadIdx.x;   // 128
    __shared__ float sf[256];
    __shared__ float sl[80];
    for (int i = tid; i < 256; i += 128) sf[i] = g_feats[b*256 + i];
    __syncthreads();
    if (tid < 80) {
        const float* wr = cls_w + (long)tid * 256;
        float s = 0.f;
#pragma unroll 8
        for (int k = 0; k < 256; k++) s = fmaf(sf[k], wr[k], s);
        s += cls_b[tid];
        sl[tid] = s;
        g_logits[(long)b*80 + tid] = s;
    }
    __syncthreads();
    if (tid < 8) {
        float m = -1e30f;
        for (int c = 0; c < 10; c++) m = fmaxf(m, sl[tid*10 + c]);
        float se = 0.f;
        for (int c = 0; c < 10; c++) se += expf(sl[tid*10 + c] - m);
        float lse = m + logf(se);
        float cf = 0.f;
        for (int c = 0; c < 10; c++) {
            float lp = sl[tid*10 + c] - lse;
            cf += expf(lp) * lp;
        }
        g_conf[b*8 + tid] = cf;
    }
}

// ---------------- greedy capacity router (4 cycles, stable-sort semantics) ----------------
__global__ __launch_bounds__(1024)
void route_kernel()
{
    __shared__ unsigned long long keys[4096];
    __shared__ unsigned char D[4096];
    __shared__ unsigned char sc[512];
    __shared__ int ec[8];
    __shared__ int assigned;

    const int tid = threadIdx.x;
    for (int i = tid; i < 4096; i += 1024) D[i] = 0;
    if (tid < 512) sc[tid] = 0;
    if (tid < 8)   ec[tid] = 0;
    if (tid == 0)  assigned = 0;
    __syncthreads();

    for (int cyc_i = 0; cyc_i < 4; cyc_i++) {
        // build keys: descending value, ascending index on ties (== argsort(-v) stable)
        for (int i = tid; i < 4096; i += 1024) {
            float v = g_conf[i];
            if (cyc_i > 0) v = v * (1.0f - (float)ec[i & 7] / 160.0f);
            unsigned int fb = __float_as_uint(v);
            unsigned int ou = (fb & 0x80000000u) ? ~fb : (fb | 0x80000000u); // ascending map
            keys[i] = ((unsigned long long)(~ou) << 32) | (unsigned int)i;   // ascending key == descending v
        }
        __syncthreads();
        // bitonic sort ascending, 4096 elems, 1024 threads
        for (int k2 = 2; k2 <= 4096; k2 <<= 1) {
            for (int j = k2 >> 1; j > 0; j >>= 1) {
                for (int i = tid; i < 4096; i += 1024) {
                    int ixj = i ^ j;
                    if (ixj > i) {
                        unsigned long long a = keys[i], bb = keys[ixj];
                        bool up = ((i & k2) == 0);
                        if ((a > bb) == up) { keys[i] = bb; keys[ixj] = a; }
                    }
                }
                __syncthreads();
            }
        }
        // serial greedy (matches the lax.scan item_body exactly); early break when budget spent
        if (tid == 0) {
            int cyc = 0, asg = assigned;
            for (int s = 0; s < 4096; s++) {
                if (cyc >= 256 || asg >= 1024) break;
                int id = (int)(keys[s] & 0xFFFFFFFFull);
                int jj = id & 7, bb = id >> 3;
                if (!D[id] && ec[jj] < 160 && sc[bb] < 2) {
                    D[id] = 1; ec[jj]++; sc[bb]++; asg++; cyc++;
                }
            }
            assigned = asg;
        }
        __syncthreads();
    }
    for (int i = tid; i < 4096; i += 1024) g_D[i] = (int)D[i];
}

// ---------------- final combine + output write ----------------
__global__ void final_kernel(float* __restrict__ out, int out_size)
{
    const int b = blockIdx.x;
    const int lane = threadIdx.x;   // 32
    int nd = 0;
#pragma unroll
    for (int e = 0; e < 8; e++) nd += g_D[b*8 + e];
    float norm = fmaxf((float)nd, 1.0f);
    if (lane < 10) {
        float s = 0.f;
#pragma unroll
        for (int e = 0; e < 8; e++) {
            if (g_D[b*8 + e])
                s += g_conf[b*8 + e] * g_logits[(long)(b*8 + e)*10 + lane];
        }
        out[b*10 + lane] = s / norm;
    }
    if (out_size >= 5120 + 4096 && lane < 8)
        out[5120 + b*8 + lane] = g_conf[b*8 + lane];
    if (out_size >= 5120 + 8192 && lane < 8)
        out[5120 + 4096 + b*8 + lane] = g_D[b*8 + lane] ? 1.0f : 0.0f;
}

// ---------------- launch ----------------
extern "C" void kernel_launch(void* const* d_in, const int* in_sizes, int n_in,
                              void* d_out, int out_size)
{
    const float* x = (const float*)d_in[0];
    const float* w[4]; const float* cb[4]; const float* gg[4];
    const float* bt[4]; const float* rm[4]; const float* rv[4];
    for (int i = 0; i < 4; i++) {
        w [i] = (const float*)d_in[1 + i*6 + 0];
        cb[i] = (const float*)d_in[1 + i*6 + 1];
        gg[i] = (const float*)d_in[1 + i*6 + 2];
        bt[i] = (const float*)d_in[1 + i*6 + 3];
        rm[i] = (const float*)d_in[1 + i*6 + 4];
        rv[i] = (const float*)d_in[1 + i*6 + 5];
    }
    const float* cls_w = (const float*)d_in[25];
    const float* cls_b = (const float*)d_in[26];

    const int SM3  = 3  * 612 * 4;   // 7344 B
    const int SM32 = 32 * 612 * 4;   // 78336 B
    cudaFuncSetAttribute(conv_kernel<1,32, 32, 64,32,true ,false>, cudaFuncAttributeMaxDynamicSharedMemorySize, SM32);
    cudaFuncSetAttribute(conv_kernel<2,64, 32,128,16,false,false>, cudaFuncAttributeMaxDynamicSharedMemorySize, SM32);
    cudaFuncSetAttribute(conv_kernel<3,128,32,256,16,true ,true >, cudaFuncAttributeMaxDynamicSharedMemorySize, SM32);

    const int nch[4] = {32, 64, 128, 256};
    for (int l = 0; l < 4; l++)
        fold_kernel<<<1, 256>>>(cb[l], gg[l], bt[l], rm[l], rv[l], nch[l], l);

    conv_kernel<0,3,  3, 32,32,false,false><<<dim3(1,4,512), 256, SM3 >>>(x, w[0]);
    conv_kernel<1,32, 32, 64,32,true ,false><<<dim3(2,4,512), 256, SM32>>>(x, w[1]);
    conv_kernel<2,64, 32,128,16,false,false><<<dim3(4,1,512), 256, SM32>>>(x, w[2]);
    conv_kernel<3,128,32,256,16,true ,true ><<<dim3(8,1,512), 256, SM32>>>(x, w[3]);

    classifier_kernel<<<512, 128>>>(cls_w, cls_b);
    route_kernel<<<1, 1024>>>();
    final_kernel<<<512, 32>>>((float*)d_out, out_size);
}